// round 6
// baseline (speedup 1.0000x reference)
#include <cuda_runtime.h>
#include <math.h>
#include <math_constants.h>
#include <stdint.h>

#define NROW 8192   // B*S
#define DIM  1024
#define SEQ  2048
#define NBATCH 4
#define HID  4096
#define CHUNKS 16
#define TCHUNK (SEQ / CHUNKS)   // 128
#define NQKV 3072

// ---------------- scratch (static device globals; no runtime alloc) ----------
__device__ uint16_t g_h_hi[(size_t)NROW * DIM];
__device__ uint16_t g_h_lo[(size_t)NROW * DIM];
__device__ uint16_t g_h2_hi[(size_t)NROW * DIM];
__device__ uint16_t g_h2_lo[(size_t)NROW * DIM];
__device__ uint16_t g_m1_hi[(size_t)NROW * HID];
__device__ uint16_t g_m1_lo[(size_t)NROW * HID];
__device__ uint16_t g_Wqkv_hi[(size_t)NQKV * DIM];
__device__ uint16_t g_Wqkv_lo[(size_t)NQKV * DIM];
__device__ uint16_t g_W1_hi[(size_t)HID * DIM];
__device__ uint16_t g_W1_lo[(size_t)HID * DIM];
__device__ uint16_t g_W2_hi[(size_t)DIM * HID];
__device__ uint16_t g_W2_lo[(size_t)DIM * HID];
__device__ float  g_qkv[(size_t)NROW * NQKV];
__device__ float  g_bqkv[NQKV];
__device__ float2 g_Qhat[(size_t)NROW * DIM];
__device__ float2 g_Mhat[(size_t)NROW * DIM];
__device__ float  g_xmid[(size_t)NROW * DIM];
__device__ float2 g_tw[512];
__device__ float2 g_part[NBATCH * CHUNKS * DIM];

// ---------------- helpers ----------------
__device__ __forceinline__ uint32_t smem_u32(const void* p) {
    uint32_t a;
    asm("{ .reg .u64 t; cvta.to.shared.u64 t, %1; cvt.u32.u64 %0, t; }" : "=r"(a) : "l"(p));
    return a;
}
// split pair (x0,x1) -> packed bf16x2 hi (low half = x0) and lo
__device__ __forceinline__ void split2(float x0, float x1, uint32_t& hi, uint32_t& lo) {
    uint32_t h;
    asm("cvt.rn.bf16x2.f32 %0, %1, %2;" : "=r"(h) : "f"(x1), "f"(x0));
    float h0 = __uint_as_float(h << 16);
    float h1 = __uint_as_float(h & 0xFFFF0000u);
    float l0 = x0 - h0;
    float l1 = x1 - h1;
    asm("cvt.rn.bf16x2.f32 %0, %1, %2;" : "=r"(lo) : "f"(l1), "f"(l0));
    hi = h;
}
__device__ __forceinline__ void mma_bf16(float* d, const uint32_t* a, const uint32_t* b) {
    asm volatile("mma.sync.aligned.m16n8k16.row.col.f32.bf16.bf16.f32 "
        "{%0,%1,%2,%3}, {%4,%5,%6,%7}, {%8,%9}, {%0,%1,%2,%3};"
        : "+f"(d[0]), "+f"(d[1]), "+f"(d[2]), "+f"(d[3])
        : "r"(a[0]), "r"(a[1]), "r"(a[2]), "r"(a[3]), "r"(b[0]), "r"(b[1]));
}
__device__ __forceinline__ void cpa16(uint32_t dst, const void* src) {
    asm volatile("cp.async.cg.shared.global [%0], [%1], 16;" :: "r"(dst), "l"(src) : "memory");
}
__device__ __forceinline__ void ldsm4(uint32_t* r, uint32_t addr) {
    asm volatile("ldmatrix.sync.aligned.m8n8.x4.shared.b16 {%0,%1,%2,%3}, [%4];"
        : "=r"(r[0]), "=r"(r[1]), "=r"(r[2]), "=r"(r[3]) : "r"(addr));
}
__device__ __forceinline__ float2 c_add(float2 a, float2 b){return make_float2(a.x+b.x,a.y+b.y);}
__device__ __forceinline__ float2 c_sub(float2 a, float2 b){return make_float2(a.x-b.x,a.y-b.y);}
__device__ __forceinline__ float2 c_mul(float2 a, float2 b){return make_float2(a.x*b.x-a.y*b.y,a.x*b.y+a.y*b.x);}
__device__ __forceinline__ float2 c_negi(float2 a){return make_float2(a.y,-a.x);}  // -i*a

// ---------------- twiddle init ----------------
__global__ void init_tw_kernel() {
    int i = threadIdx.x;
    double th = -2.0 * CUDART_PI * (double)i / 1024.0;
    g_tw[i] = make_float2((float)cos(th), (float)sin(th));
}

// ---------------- bias concat ----------------
__global__ void bias_concat_kernel(const float* bq, const float* bk, const float* bv) {
    int i = blockIdx.x * 256 + threadIdx.x;
    float v = (i < 1024) ? bq[i] : (i < 2048) ? bk[i - 1024] : bv[i - 2048];
    g_bqkv[i] = v;
}

// ---------------- weight transpose + bf16 split ----------------
__global__ __launch_bounds__(256) void transpose_split_kernel(
    const float* __restrict__ in, uint16_t* __restrict__ ohi,
    uint16_t* __restrict__ olo, int R, int C)
{
    __shared__ float t[32][33];
    int bx = blockIdx.x, by = blockIdx.y;
    int x = bx * 32 + threadIdx.x;
    int y0 = by * 32 + threadIdx.y;
    #pragma unroll
    for (int j = 0; j < 32; j += 8)
        t[threadIdx.y + j][threadIdx.x] = in[(size_t)(y0 + j) * C + x];
    __syncthreads();
    int tl = threadIdx.y * 32 + threadIdx.x;
    int kp = tl & 15;
    int nr0 = tl >> 4;
    uint32_t* hw32 = (uint32_t*)ohi;
    uint32_t* lw32 = (uint32_t*)olo;
    #pragma unroll
    for (int rep = 0; rep < 2; rep++) {
        int nrel = nr0 + rep * 16;
        size_t n = (size_t)bx * 32 + nrel;
        int kg = by * 32 + kp * 2;
        uint32_t hw, lw;
        split2(t[kp * 2][nrel], t[kp * 2 + 1][nrel], hw, lw);
        size_t widx = (n * (size_t)R + kg) >> 1;
        hw32[widx] = hw;
        lw32[widx] = lw;
    }
}

// ---------------- block reduction ----------------
__device__ __forceinline__ float2 block_reduce2(float2 v, float2* sh) {
    int tid = threadIdx.x;
    sh[tid] = v;
    __syncthreads();
    #pragma unroll
    for (int s = 128; s > 0; s >>= 1) {
        if (tid < s) {
            sh[tid].x += sh[tid + s].x;
            sh[tid].y += sh[tid + s].y;
        }
        __syncthreads();
    }
    float2 r = sh[0];
    __syncthreads();
    return r;
}

// ---------------- LayerNorm 1 -> bf16 hi/lo planes ----------------
__global__ __launch_bounds__(256) void ln_split_kernel(
    const float* __restrict__ x, const float* __restrict__ g,
    const float* __restrict__ b, uint16_t* __restrict__ ohi,
    uint16_t* __restrict__ olo)
{
    __shared__ float2 red[256];
    size_t row = blockIdx.x;
    int tid = threadIdx.x;
    float4 v = ((const float4*)(x + row * DIM))[tid];
    float s = v.x + v.y + v.z + v.w;
    float ss = v.x * v.x + v.y * v.y + v.z * v.z + v.w * v.w;
    float2 tot = block_reduce2(make_float2(s, ss), red);
    float mu = tot.x * (1.0f / DIM);
    float var = tot.y * (1.0f / DIM) - mu * mu;
    float rstd = rsqrtf(var + 1e-5f);
    float4 gg = ((const float4*)g)[tid];
    float4 bb = ((const float4*)b)[tid];
    float y0 = (v.x - mu) * rstd * gg.x + bb.x;
    float y1 = (v.y - mu) * rstd * gg.y + bb.y;
    float y2 = (v.z - mu) * rstd * gg.z + bb.z;
    float y3 = (v.w - mu) * rstd * gg.w + bb.w;
    uint32_t h0, l0, h1, l1;
    split2(y0, y1, h0, l0);
    split2(y2, y3, h1, l1);
    uint32_t* hw = (uint32_t*)ohi;
    uint32_t* lw = (uint32_t*)olo;
    size_t wb = row * 512 + tid * 2;
    hw[wb] = h0; hw[wb + 1] = h1;
    lw[wb] = l0; lw[wb + 1] = l1;
}

// -------- 1024-pt radix-4 Stockham FFT (5 stages), 256 threads -------------
// Derived by fusing two radix-2 Stockham stages; forward DFT, natural order.
__device__ __forceinline__ float2* fft1024(float2* bufA, float2* bufB) {
    float2* x = bufA;
    float2* y = bufB;
    int n4 = 256, s = 1;
    #pragma unroll
    for (int st = 0; st < 5; st++) {
        __syncthreads();
        int i = threadIdx.x;
        int p = i / s;
        int q = i - p * s;
        float2 w1 = g_tw[p * s];
        float2 w2 = g_tw[2 * p * s];
        float2 x0 = x[q + s * p];
        float2 x1 = x[q + s * (p + n4)];
        float2 x2 = x[q + s * (p + 2 * n4)];
        float2 x3 = x[q + s * (p + 3 * n4)];
        float2 za0 = c_add(x0, x2);
        float2 za1 = c_mul(c_sub(x0, x2), w1);
        float2 zb0 = c_add(x1, x3);
        float2 zb1 = c_mul(c_negi(c_sub(x1, x3)), w1);
        int ob = q + s * 4 * p;
        y[ob]         = c_add(za0, zb0);
        y[ob + s]     = c_add(za1, zb1);
        y[ob + 2 * s] = c_mul(c_sub(za0, zb0), w2);
        y[ob + 3 * s] = c_mul(c_sub(za1, zb1), w2);
        float2* t = x; x = y; y = t;
        n4 >>= 2; s <<= 2;
    }
    __syncthreads();
    return x;   // bufB after 5 swaps
}

// ---------------- forward FFT + unit-magnitude normalize ----------------
__global__ __launch_bounds__(256) void fft_norm_kernel(
    const float* __restrict__ in, int istride, int ioff,
    float2* __restrict__ out, int mode)
{
    __shared__ __align__(16) float2 bufA[1024];
    __shared__ __align__(16) float2 bufB[1024];
    size_t row = blockIdx.x;
    const float* ip = in + row * istride + ioff;
    #pragma unroll
    for (int j = 0; j < 4; j++) {
        int idx = threadIdx.x + j * 256;
        bufA[idx] = make_float2(ip[idx], 0.f);
    }
    float2* res = fft1024(bufA, bufB);
    float2* op = out + row * DIM;
    #pragma unroll
    for (int j = 0; j < 4; j++) {
        int idx = threadIdx.x + j * 256;
        float2 f = res[idx];
        float mag = sqrtf(f.x * f.x + f.y * f.y);
        float inv = 1.0f / fmaxf(mag, 1e-8f);
        f.x *= inv; f.y *= inv;
        if (mode == 0) {
            op[idx] = f;
        } else {
            float2 k = op[idx];
            op[idx] = make_float2(k.x * f.x - k.y * f.y,
                                  k.x * f.y + k.y * f.x);
        }
    }
}

// ---------------- chain pass A: per-chunk partial sums ----------------
__global__ __launch_bounds__(256) void chain_partial_kernel() {
    int gid = blockIdx.x * 256 + threadIdx.x;
    int bin = gid & 1023;
    int chunk = (gid >> 10) & (CHUNKS - 1);
    int b = gid >> 14;
    size_t base = ((size_t)b * SEQ + (size_t)chunk * TCHUNK) * DIM + bin;
    float2 s = make_float2(0.f, 0.f);
    #pragma unroll 4
    for (int i = 0; i < TCHUNK; i++) {
        float2 p = g_Mhat[base + (size_t)i * DIM];
        s.x += p.x; s.y += p.y;
    }
    g_part[gid] = s;
}

// ---------------- chain pass B: scan within chunk + apply conj(Q̂) --------
__global__ __launch_bounds__(256) void chain_apply_kernel() {
    int gid = blockIdx.x * 256 + threadIdx.x;
    int bin = gid & 1023;
    int chunk = (gid >> 10) & (CHUNKS - 1);
    int b = gid >> 14;
    float2 acc = make_float2(0.f, 0.f);
    for (int c = 0; c < chunk; c++) {
        float2 p = g_part[((b * CHUNKS) + c) * 1024 + bin];
        acc.x += p.x; acc.y += p.y;
    }
    size_t base = ((size_t)b * SEQ + (size_t)chunk * TCHUNK) * DIM + bin;
    #pragma unroll 4
    for (int i = 0; i < TCHUNK; i++) {
        size_t off = base + (size_t)i * DIM;
        float2 p = g_Mhat[off];
        acc.x += p.x; acc.y += p.y;
        float2 q = g_Qhat[off];
        g_Mhat[off] = make_float2(acc.x * q.x + acc.y * q.y,
                                  acc.y * q.x - acc.x * q.y);
    }
}

// ------- inverse FFT + residual + LN2, emits xmid fp32 and h2 bf16 planes ----
__global__ __launch_bounds__(256) void ifft_res_ln_split_kernel(
    const float* __restrict__ x, const float* __restrict__ g,
    const float* __restrict__ b, uint16_t* __restrict__ ohi,
    uint16_t* __restrict__ olo)
{
    __shared__ __align__(16) float2 bufA[1024];
    __shared__ __align__(16) float2 bufB[1024];
    size_t row = blockIdx.x;
    int tid = threadIdx.x;
    const float2* mp = g_Mhat + row * DIM;
    #pragma unroll
    for (int j = 0; j < 4; j++) {
        int idx = tid + j * 256;
        float2 m = mp[idx];
        bufA[idx] = make_float2(m.x, -m.y);
    }
    float2* res = fft1024(bufA, bufB);   // = bufB
    float mixed[4];
    #pragma unroll
    for (int j = 0; j < 4; j++) mixed[j] = res[tid + j * 256].x * (1.0f / 1024.0f);
    __syncthreads();
    float* sbuf = (float*)bufA;          // bufA is dead now
    const float* xp = x + row * DIM;
    float* xo = g_xmid + row * DIM;
    float s = 0.f, ss = 0.f;
    #pragma unroll
    for (int j = 0; j < 4; j++) {
        int idx = tid + j * 256;
        float v = xp[idx] + mixed[j];
        xo[idx] = v;
        sbuf[idx] = v;
        s += v; ss += v * v;
    }
    __syncthreads();                      // mixed reads of bufB done before reuse
    float2 tot = block_reduce2(make_float2(s, ss), bufB);
    float mu = tot.x * (1.0f / DIM);
    float var = tot.y * (1.0f / DIM) - mu * mu;
    float rstd = rsqrtf(var + 1e-5f);
    float4 vv = ((const float4*)sbuf)[tid];
    float4 gg = ((const float4*)g)[tid];
    float4 bb = ((const float4*)b)[tid];
    float y0 = (vv.x - mu) * rstd * gg.x + bb.x;
    float y1 = (vv.y - mu) * rstd * gg.y + bb.y;
    float y2 = (vv.z - mu) * rstd * gg.z + bb.z;
    float y3 = (vv.w - mu) * rstd * gg.w + bb.w;
    uint32_t h0, l0, h1, l1;
    split2(y0, y1, h0, l0);
    split2(y2, y3, h1, l1);
    uint32_t* hw = (uint32_t*)ohi;
    uint32_t* lw = (uint32_t*)olo;
    size_t wb = row * 512 + tid * 2;
    hw[wb] = h0; hw[wb + 1] = h1;
    lw[wb] = l0; lw[wb + 1] = l1;
}

// ================== bf16x3 mma.sync GEMM, ldmatrix fragments ==================
// 128x128 CTA tile, BK=32, 4 warps (2x2), warp tile 64x64, 2-stage cp.async.
// SMEM per stage: Ahi|Alo|Bhi|Blo planes, 128 rows x 80B stride (64B data).
// Fragments via ldmatrix.x4 (conflict-free with 80B row stride).
// EPI: 0 = bias -> Cf ; 1 = bias + GELU -> Chi/Clo planes ; 2 = bias+res -> Cf
#define PLANE_B 10240u                    // bytes per plane
#define STAGE_B 40960u                    // bytes per stage (4 planes)
#define SMEM_GEMM (2 * STAGE_B)           // 81920

template<int EPI>
__global__ __launch_bounds__(128) void mma_gemm(
    const uint16_t* __restrict__ Ahi, const uint16_t* __restrict__ Alo,
    const uint16_t* __restrict__ Bhi, const uint16_t* __restrict__ Blo,
    const float* __restrict__ bias, const float* __restrict__ res,
    float* __restrict__ Cf, uint32_t* __restrict__ Chi, uint32_t* __restrict__ Clo,
    int N, int K)
{
    extern __shared__ uint32_t smu[];
    uint32_t su = smem_u32(smu);

    int tid = threadIdx.x;
    int wid = tid >> 5;
    int lane = tid & 31;
    int wm = wid & 1;
    int wn = wid >> 1;
    int bx = blockIdx.x, by = blockIdx.y;
    int gq = lane >> 2, tq = lane & 3;

    int frow = tid;   // 0..127
    const uint16_t* aH = Ahi + (size_t)(by * 128 + frow) * K;
    const uint16_t* aL = Alo + (size_t)(by * 128 + frow) * K;
    const uint16_t* bH = Bhi + (size_t)(bx * 128 + frow) * K;
    const uint16_t* bL = Blo + (size_t)(bx * 128 + frow) * K;

    #define LOAD_STAGE(s, k0) do { \
        uint32_t _d = su + (uint32_t)(s) * STAGE_B + (uint32_t)frow * 80u; \
        _Pragma("unroll") \
        for (int c = 0; c < 4; c++) { \
            cpa16(_d + c * 16,               aH + (k0) + c * 8); \
            cpa16(_d + PLANE_B + c * 16,     aL + (k0) + c * 8); \
            cpa16(_d + 2 * PLANE_B + c * 16, bH + (k0) + c * 8); \
            cpa16(_d + 3 * PLANE_B + c * 16, bL + (k0) + c * 8); \
        } \
        asm volatile("cp.async.commit_group;" ::: "memory"); \
    } while (0)

    float acc[4][8][4];
    #pragma unroll
    for (int mt = 0; mt < 4; mt++)
        #pragma unroll
        for (int nt = 0; nt < 8; nt++)
            #pragma unroll
            for (int i = 0; i < 4; i++) acc[mt][nt][i] = 0.f;

    int KT = K >> 5;
    LOAD_STAGE(0, 0);

    // ldmatrix per-lane source address offsets (within a plane)
    uint32_t lrow = (uint32_t)(lane & 15);
    uint32_t lcol = (uint32_t)(lane >> 4) * 16u;
    uint32_t aLdsm = (uint32_t)(wm * 64) * 80u + lrow * 80u + lcol;
    uint32_t bLdsm = (uint32_t)(wn * 64) * 80u + lrow * 80u + lcol;

    for (int it = 0; it < KT; it++) {
        asm volatile("cp.async.wait_group 0;" ::: "memory");
        __syncthreads();
        if (it + 1 < KT) LOAD_STAGE((it + 1) & 1, (it + 1) * 32);

        uint32_t sb = su + (uint32_t)(it & 1) * STAGE_B;

        #pragma unroll
        for (int ks = 0; ks < 2; ks++) {
            uint32_t ksb = (uint32_t)ks * 32u;
            uint32_t ah[4][4], al[4][4], bh4[4][4], bl4[4][4];
            #pragma unroll
            for (int mt = 0; mt < 4; mt++) {
                uint32_t ad = sb + aLdsm + (uint32_t)mt * (16u * 80u) + ksb;
                ldsm4(ah[mt], ad);
                ldsm4(al[mt], ad + PLANE_B);
            }
            #pragma unroll
            for (int ntp = 0; ntp < 4; ntp++) {
                uint32_t bd = sb + 2 * PLANE_B + bLdsm + (uint32_t)ntp * (16u * 80u) + ksb;
                ldsm4(bh4[ntp], bd);
                ldsm4(bl4[ntp], bd + PLANE_B);
            }
            // passes 1+2: (hi_a + lo_a) * hi_b
            #pragma unroll
            for (int mt = 0; mt < 4; mt++)
                #pragma unroll
                for (int nt = 0; nt < 8; nt++) {
                    uint32_t bb[2] = { bh4[nt >> 1][nt & 1], bh4[nt >> 1][(nt & 1) + 2] };
                    mma_bf16(acc[mt][nt], ah[mt], bb);
                    mma_bf16(acc[mt][nt], al[mt], bb);
                }
            // pass 3: hi_a * lo_b
            #pragma unroll
            for (int mt = 0; mt < 4; mt++)
                #pragma unroll
                for (int nt = 0; nt < 8; nt++) {
                    uint32_t bb[2] = { bl4[nt >> 1][nt & 1], bl4[nt >> 1][(nt & 1) + 2] };
                    mma_bf16(acc[mt][nt], ah[mt], bb);
                }
        }
        __syncthreads();
    }

    // ---- epilogue ----
    #pragma unroll
    for (int mt = 0; mt < 4; mt++) {
        #pragma unroll
        for (int nt = 0; nt < 8; nt++) {
            int r0 = by * 128 + wm * 64 + mt * 16 + gq;
            int c0 = bx * 128 + wn * 64 + nt * 8 + tq * 2;
            float b0 = bias[c0], b1 = bias[c0 + 1];
            #pragma unroll
            for (int half = 0; half < 2; half++) {
                size_t r = r0 + half * 8;
                float v0 = acc[mt][nt][half * 2 + 0] + b0;
                float v1 = acc[mt][nt][half * 2 + 1] + b1;
                if (EPI == 1) {
                    v0 = 0.5f * v0 * (1.0f + erff(v0 * 0.70710678118654752f));
                    v1 = 0.5f * v1 * (1.0f + erff(v1 * 0.70710678118654752f));
                    uint32_t hw, lw;
                    split2(v0, v1, hw, lw);
                    size_t widx = (r * (size_t)N + c0) >> 1;
                    Chi[widx] = hw;
                    Clo[widx] = lw;
                } else {
                    if (EPI == 2) {
                        float2 rv = *(const float2*)(res + r * (size_t)N + c0);
                        v0 += rv.x; v1 += rv.y;
                    }
                    float2 o; o.x = v0; o.y = v1;
                    *(float2*)(Cf + r * (size_t)N + c0) = o;
                }
            }
        }
    }
}

// ---------------- launch ----------------
extern "C" void kernel_launch(void* const* d_in, const int* in_sizes, int n_in,
                              void* d_out, int out_size)
{
    const float* x     = (const float*)d_in[0];
    const float* Wq    = (const float*)d_in[1];
    const float* bq    = (const float*)d_in[2];
    const float* Wk    = (const float*)d_in[3];
    const float* bk    = (const float*)d_in[4];
    const float* Wv    = (const float*)d_in[5];
    const float* bv    = (const float*)d_in[6];
    const float* ln1_g = (const float*)d_in[7];
    const float* ln1_b = (const float*)d_in[8];
    const float* ln2_g = (const float*)d_in[9];
    const float* ln2_b = (const float*)d_in[10];
    const float* W1    = (const float*)d_in[11];
    const float* b1    = (const float*)d_in[12];
    const float* W2    = (const float*)d_in[13];
    const float* b2    = (const float*)d_in[14];
    float* out = (float*)d_out;

    uint16_t *hHi, *hLo, *h2Hi, *h2Lo, *m1Hi, *m1Lo;
    uint16_t *WqkvHi, *WqkvLo, *W1Hi, *W1Lo, *W2Hi, *W2Lo;
    float *qkv, *xmid, *bqkv;
    float2 *Qhat, *Mhat;
    cudaGetSymbolAddress((void**)&hHi,   g_h_hi);
    cudaGetSymbolAddress((void**)&hLo,   g_h_lo);
    cudaGetSymbolAddress((void**)&h2Hi,  g_h2_hi);
    cudaGetSymbolAddress((void**)&h2Lo,  g_h2_lo);
    cudaGetSymbolAddress((void**)&m1Hi,  g_m1_hi);
    cudaGetSymbolAddress((void**)&m1Lo,  g_m1_lo);
    cudaGetSymbolAddress((void**)&WqkvHi, g_Wqkv_hi);
    cudaGetSymbolAddress((void**)&WqkvLo, g_Wqkv_lo);
    cudaGetSymbolAddress((void**)&W1Hi,  g_W1_hi);
    cudaGetSymbolAddress((void**)&W1Lo,  g_W1_lo);
    cudaGetSymbolAddress((void**)&W2Hi,  g_W2_hi);
    cudaGetSymbolAddress((void**)&W2Lo,  g_W2_lo);
    cudaGetSymbolAddress((void**)&qkv,   g_qkv);
    cudaGetSymbolAddress((void**)&xmid,  g_xmid);
    cudaGetSymbolAddress((void**)&bqkv,  g_bqkv);
    cudaGetSymbolAddress((void**)&Qhat,  g_Qhat);
    cudaGetSymbolAddress((void**)&Mhat,  g_Mhat);

    cudaFuncSetAttribute(mma_gemm<0>, cudaFuncAttributeMaxDynamicSharedMemorySize, SMEM_GEMM);
    cudaFuncSetAttribute(mma_gemm<1>, cudaFuncAttributeMaxDynamicSharedMemorySize, SMEM_GEMM);
    cudaFuncSetAttribute(mma_gemm<2>, cudaFuncAttributeMaxDynamicSharedMemorySize, SMEM_GEMM);

    init_tw_kernel<<<1, 512>>>();
    bias_concat_kernel<<<NQKV / 256, 256>>>(bq, bk, bv);

    // weights -> transposed bf16 hi/lo planes
    transpose_split_kernel<<<dim3(32, 32), dim3(32, 8)>>>(Wq, WqkvHi, WqkvLo, DIM, DIM);
    transpose_split_kernel<<<dim3(32, 32), dim3(32, 8)>>>(Wk, WqkvHi + (size_t)1024 * DIM, WqkvLo + (size_t)1024 * DIM, DIM, DIM);
    transpose_split_kernel<<<dim3(32, 32), dim3(32, 8)>>>(Wv, WqkvHi + (size_t)2048 * DIM, WqkvLo + (size_t)2048 * DIM, DIM, DIM);
    transpose_split_kernel<<<dim3(128, 32), dim3(32, 8)>>>(W1, W1Hi, W1Lo, DIM, HID);
    transpose_split_kernel<<<dim3(32, 128), dim3(32, 8)>>>(W2, W2Hi, W2Lo, HID, DIM);

    // LN1 -> h planes
    ln_split_kernel<<<NROW, 256>>>(x, ln1_g, ln1_b, hHi, hLo);

    // fused QKV projection
    mma_gemm<0><<<dim3(NQKV / 128, NROW / 128), 128, SMEM_GEMM>>>(
        hHi, hLo, WqkvHi, WqkvLo, bqkv, nullptr, qkv, nullptr, nullptr, NQKV, DIM);

    // FFT + unit-magnitude normalization
    fft_norm_kernel<<<NROW, 256>>>(qkv, NQKV, 0,    Qhat, 0);
    fft_norm_kernel<<<NROW, 256>>>(qkv, NQKV, 1024, Mhat, 0);
    fft_norm_kernel<<<NROW, 256>>>(qkv, NQKV, 2048, Mhat, 1);

    // causal cumsum in Fourier domain, fused * conj(Q̂)
    chain_partial_kernel<<<(NBATCH * CHUNKS * DIM) / 256, 256>>>();
    chain_apply_kernel<<<(NBATCH * CHUNKS * DIM) / 256, 256>>>();

    // inverse FFT + residual + LN2 (emits xmid fp32 + h2 planes)
    ifft_res_ln_split_kernel<<<NROW, 256>>>(x, ln2_g, ln2_b, h2Hi, h2Lo);

    // MLP
    mma_gemm<1><<<dim3(HID / 128, NROW / 128), 128, SMEM_GEMM>>>(
        h2Hi, h2Lo, W1Hi, W1Lo, b1, nullptr, nullptr,
        (uint32_t*)m1Hi, (uint32_t*)m1Lo, HID, DIM);
    mma_gemm<2><<<dim3(DIM / 128, NROW / 128), 128, SMEM_GEMM>>>(
        m1Hi, m1Lo, W2Hi, W2Lo, b2, xmid, out, nullptr, nullptr, DIM, HID);

    (void)in_sizes; (void)n_in; (void)out_size;
}

// round 7
// speedup vs baseline: 1.1054x; 1.1054x over previous
#include <cuda_runtime.h>
#include <math.h>
#include <math_constants.h>
#include <stdint.h>

#define NROW 8192   // B*S
#define DIM  1024
#define SEQ  2048
#define NBATCH 4
#define HID  4096
#define CHUNKS 16
#define TCHUNK (SEQ / CHUNKS)   // 128
#define NQKV 3072

// ---------------- scratch (static device globals; no runtime alloc) ----------
__device__ uint16_t g_h_hi[(size_t)NROW * DIM];
__device__ uint16_t g_h_lo[(size_t)NROW * DIM];
__device__ uint16_t g_h2_hi[(size_t)NROW * DIM];
__device__ uint16_t g_h2_lo[(size_t)NROW * DIM];
__device__ uint16_t g_m1_hi[(size_t)NROW * HID];
__device__ uint16_t g_m1_lo[(size_t)NROW * HID];
__device__ uint16_t g_Wqkv_hi[(size_t)NQKV * DIM];
__device__ uint16_t g_Wqkv_lo[(size_t)NQKV * DIM];
__device__ uint16_t g_W1_hi[(size_t)HID * DIM];
__device__ uint16_t g_W1_lo[(size_t)HID * DIM];
__device__ uint16_t g_W2_hi[(size_t)DIM * HID];
__device__ uint16_t g_W2_lo[(size_t)DIM * HID];
__device__ float  g_qkv[(size_t)NROW * NQKV];
__device__ float  g_bqkv[NQKV];
__device__ float2 g_Qhat[(size_t)NROW * DIM];
__device__ float2 g_Mhat[(size_t)NROW * DIM];
__device__ float  g_xmid[(size_t)NROW * DIM];
__device__ float2 g_tw[512];
__device__ float2 g_part[NBATCH * CHUNKS * DIM];

// ---------------- helpers ----------------
__device__ __forceinline__ uint32_t smem_u32(const void* p) {
    uint32_t a;
    asm("{ .reg .u64 t; cvta.to.shared.u64 t, %1; cvt.u32.u64 %0, t; }" : "=r"(a) : "l"(p));
    return a;
}
// split pair (x0,x1) -> packed bf16x2 hi (low half = x0) and lo
__device__ __forceinline__ void split2(float x0, float x1, uint32_t& hi, uint32_t& lo) {
    uint32_t h;
    asm("cvt.rn.bf16x2.f32 %0, %1, %2;" : "=r"(h) : "f"(x1), "f"(x0));
    float h0 = __uint_as_float(h << 16);
    float h1 = __uint_as_float(h & 0xFFFF0000u);
    float l0 = x0 - h0;
    float l1 = x1 - h1;
    asm("cvt.rn.bf16x2.f32 %0, %1, %2;" : "=r"(lo) : "f"(l1), "f"(l0));
    hi = h;
}
__device__ __forceinline__ void mma_bf16(float* d, const uint32_t* a, const uint32_t* b) {
    asm volatile("mma.sync.aligned.m16n8k16.row.col.f32.bf16.bf16.f32 "
        "{%0,%1,%2,%3}, {%4,%5,%6,%7}, {%8,%9}, {%0,%1,%2,%3};"
        : "+f"(d[0]), "+f"(d[1]), "+f"(d[2]), "+f"(d[3])
        : "r"(a[0]), "r"(a[1]), "r"(a[2]), "r"(a[3]), "r"(b[0]), "r"(b[1]));
}
__device__ __forceinline__ void cpa16(uint32_t dst, const void* src) {
    asm volatile("cp.async.cg.shared.global [%0], [%1], 16;" :: "r"(dst), "l"(src) : "memory");
}

// ---------------- twiddle init ----------------
__global__ void init_tw_kernel() {
    int i = threadIdx.x;
    double th = -2.0 * CUDART_PI * (double)i / 1024.0;
    g_tw[i] = make_float2((float)cos(th), (float)sin(th));
}

// ---------------- bias concat ----------------
__global__ void bias_concat_kernel(const float* bq, const float* bk, const float* bv) {
    int i = blockIdx.x * 256 + threadIdx.x;
    float v = (i < 1024) ? bq[i] : (i < 2048) ? bk[i - 1024] : bv[i - 2048];
    g_bqkv[i] = v;
}

// ---------------- weight transpose + bf16 split ----------------
__global__ __launch_bounds__(256) void transpose_split_kernel(
    const float* __restrict__ in, uint16_t* __restrict__ ohi,
    uint16_t* __restrict__ olo, int R, int C)
{
    __shared__ float t[32][33];
    int bx = blockIdx.x, by = blockIdx.y;
    int x = bx * 32 + threadIdx.x;
    int y0 = by * 32 + threadIdx.y;
    #pragma unroll
    for (int j = 0; j < 32; j += 8)
        t[threadIdx.y + j][threadIdx.x] = in[(size_t)(y0 + j) * C + x];
    __syncthreads();
    int tl = threadIdx.y * 32 + threadIdx.x;
    int kp = tl & 15;
    int nr0 = tl >> 4;
    uint32_t* hw32 = (uint32_t*)ohi;
    uint32_t* lw32 = (uint32_t*)olo;
    #pragma unroll
    for (int rep = 0; rep < 2; rep++) {
        int nrel = nr0 + rep * 16;
        size_t n = (size_t)bx * 32 + nrel;
        int kg = by * 32 + kp * 2;
        uint32_t hw, lw;
        split2(t[kp * 2][nrel], t[kp * 2 + 1][nrel], hw, lw);
        size_t widx = (n * (size_t)R + kg) >> 1;
        hw32[widx] = hw;
        lw32[widx] = lw;
    }
}

// ---------------- block reduction ----------------
__device__ __forceinline__ float2 block_reduce2(float2 v, float2* sh) {
    int tid = threadIdx.x;
    sh[tid] = v;
    __syncthreads();
    #pragma unroll
    for (int s = 128; s > 0; s >>= 1) {
        if (tid < s) {
            sh[tid].x += sh[tid + s].x;
            sh[tid].y += sh[tid + s].y;
        }
        __syncthreads();
    }
    float2 r = sh[0];
    __syncthreads();
    return r;
}

// ---------------- LayerNorm 1 -> bf16 hi/lo planes ----------------
__global__ __launch_bounds__(256) void ln_split_kernel(
    const float* __restrict__ x, const float* __restrict__ g,
    const float* __restrict__ b, uint16_t* __restrict__ ohi,
    uint16_t* __restrict__ olo)
{
    __shared__ float2 red[256];
    size_t row = blockIdx.x;
    int tid = threadIdx.x;
    float4 v = ((const float4*)(x + row * DIM))[tid];
    float s = v.x + v.y + v.z + v.w;
    float ss = v.x * v.x + v.y * v.y + v.z * v.z + v.w * v.w;
    float2 tot = block_reduce2(make_float2(s, ss), red);
    float mu = tot.x * (1.0f / DIM);
    float var = tot.y * (1.0f / DIM) - mu * mu;
    float rstd = rsqrtf(var + 1e-5f);
    float4 gg = ((const float4*)g)[tid];
    float4 bb = ((const float4*)b)[tid];
    float y0 = (v.x - mu) * rstd * gg.x + bb.x;
    float y1 = (v.y - mu) * rstd * gg.y + bb.y;
    float y2 = (v.z - mu) * rstd * gg.z + bb.z;
    float y3 = (v.w - mu) * rstd * gg.w + bb.w;
    uint32_t h0, l0, h1, l1;
    split2(y0, y1, h0, l0);
    split2(y2, y3, h1, l1);
    uint32_t* hw = (uint32_t*)ohi;
    uint32_t* lw = (uint32_t*)olo;
    size_t wb = row * 512 + tid * 2;
    hw[wb] = h0; hw[wb + 1] = h1;
    lw[wb] = l0; lw[wb + 1] = l1;
}

// ---------------- 1024-pt radix-2 Stockham FFT (proven R5 version) ----------
__device__ __forceinline__ float2* fft1024(float2* bufA, float2* bufB) {
    float2* x = bufA;
    float2* y = bufB;
    int n = 1024, s = 1;
    #pragma unroll
    for (int st = 0; st < 10; st++) {
        int m = n >> 1;
        __syncthreads();
        #pragma unroll
        for (int j = 0; j < 2; j++) {
            int i = threadIdx.x + j * 256;
            int p = i / s;
            int q = i - p * s;
            float2 w = g_tw[p * s];
            float2 a = x[q + s * p];
            float2 b = x[q + s * (p + m)];
            float2 sum = make_float2(a.x + b.x, a.y + b.y);
            float2 dif = make_float2(a.x - b.x, a.y - b.y);
            y[q + s * (2 * p)]     = sum;
            y[q + s * (2 * p + 1)] = make_float2(dif.x * w.x - dif.y * w.y,
                                                 dif.x * w.y + dif.y * w.x);
        }
        float2* t = x; x = y; y = t;
        n >>= 1; s <<= 1;
    }
    __syncthreads();
    return x;   // bufA
}

// -------- fused QKV FFT: Q̂ -> g_Qhat ; K̂·V̂ -> g_Mhat (one block per row) ----
__global__ __launch_bounds__(256) void fft_qkv_kernel() {
    __shared__ __align__(16) float2 bufA[1024];
    __shared__ __align__(16) float2 bufB[1024];
    __shared__ __align__(16) float2 kbuf[1024];
    size_t row = blockIdx.x;
    int tid = threadIdx.x;
    const float* base = g_qkv + row * NQKV;

    // --- Q ---
    #pragma unroll
    for (int j = 0; j < 4; j++) {
        int idx = tid + j * 256;
        bufA[idx] = make_float2(base[idx], 0.f);
    }
    float2* res = fft1024(bufA, bufB);
    float2* qp = g_Qhat + row * DIM;
    #pragma unroll
    for (int j = 0; j < 4; j++) {
        int idx = tid + j * 256;
        float2 f = res[idx];
        float inv = 1.0f / fmaxf(sqrtf(f.x * f.x + f.y * f.y), 1e-8f);
        qp[idx] = make_float2(f.x * inv, f.y * inv);
    }
    __syncthreads();

    // --- K ---
    #pragma unroll
    for (int j = 0; j < 4; j++) {
        int idx = tid + j * 256;
        bufA[idx] = make_float2(base[1024 + idx], 0.f);
    }
    res = fft1024(bufA, bufB);
    #pragma unroll
    for (int j = 0; j < 4; j++) {
        int idx = tid + j * 256;
        float2 f = res[idx];
        float inv = 1.0f / fmaxf(sqrtf(f.x * f.x + f.y * f.y), 1e-8f);
        kbuf[idx] = make_float2(f.x * inv, f.y * inv);
    }
    __syncthreads();

    // --- V, multiply by K̂ ---
    #pragma unroll
    for (int j = 0; j < 4; j++) {
        int idx = tid + j * 256;
        bufA[idx] = make_float2(base[2048 + idx], 0.f);
    }
    res = fft1024(bufA, bufB);
    float2* mp = g_Mhat + row * DIM;
    #pragma unroll
    for (int j = 0; j < 4; j++) {
        int idx = tid + j * 256;
        float2 f = res[idx];
        float inv = 1.0f / fmaxf(sqrtf(f.x * f.x + f.y * f.y), 1e-8f);
        f.x *= inv; f.y *= inv;
        float2 k = kbuf[idx];
        mp[idx] = make_float2(k.x * f.x - k.y * f.y,
                              k.x * f.y + k.y * f.x);
    }
}

// ---------------- chain pass A: per-chunk partial sums ----------------
__global__ __launch_bounds__(256) void chain_partial_kernel() {
    int gid = blockIdx.x * 256 + threadIdx.x;
    int bin = gid & 1023;
    int chunk = (gid >> 10) & (CHUNKS - 1);
    int b = gid >> 14;
    size_t base = ((size_t)b * SEQ + (size_t)chunk * TCHUNK) * DIM + bin;
    float2 s = make_float2(0.f, 0.f);
    #pragma unroll 4
    for (int i = 0; i < TCHUNK; i++) {
        float2 p = g_Mhat[base + (size_t)i * DIM];
        s.x += p.x; s.y += p.y;
    }
    g_part[gid] = s;
}

// ---------------- chain pass B: scan within chunk + apply conj(Q̂) --------
__global__ __launch_bounds__(256) void chain_apply_kernel() {
    int gid = blockIdx.x * 256 + threadIdx.x;
    int bin = gid & 1023;
    int chunk = (gid >> 10) & (CHUNKS - 1);
    int b = gid >> 14;
    float2 acc = make_float2(0.f, 0.f);
    for (int c = 0; c < chunk; c++) {
        float2 p = g_part[((b * CHUNKS) + c) * 1024 + bin];
        acc.x += p.x; acc.y += p.y;
    }
    size_t base = ((size_t)b * SEQ + (size_t)chunk * TCHUNK) * DIM + bin;
    #pragma unroll 4
    for (int i = 0; i < TCHUNK; i++) {
        size_t off = base + (size_t)i * DIM;
        float2 p = g_Mhat[off];
        acc.x += p.x; acc.y += p.y;
        float2 q = g_Qhat[off];
        g_Mhat[off] = make_float2(acc.x * q.x + acc.y * q.y,
                                  acc.y * q.x - acc.x * q.y);
    }
}

// ------- inverse FFT + residual + LN2, emits xmid fp32 and h2 bf16 planes ----
__global__ __launch_bounds__(256) void ifft_res_ln_split_kernel(
    const float* __restrict__ x, const float* __restrict__ g,
    const float* __restrict__ b, uint16_t* __restrict__ ohi,
    uint16_t* __restrict__ olo)
{
    __shared__ __align__(16) float2 bufA[1024];
    __shared__ __align__(16) float2 bufB[1024];
    size_t row = blockIdx.x;
    int tid = threadIdx.x;
    const float2* mp = g_Mhat + row * DIM;
    #pragma unroll
    for (int j = 0; j < 4; j++) {
        int idx = tid + j * 256;
        float2 m = mp[idx];
        bufA[idx] = make_float2(m.x, -m.y);
    }
    float2* res = fft1024(bufA, bufB);
    float mixed[4];
    #pragma unroll
    for (int j = 0; j < 4; j++) mixed[j] = res[tid + j * 256].x * (1.0f / 1024.0f);
    __syncthreads();
    float* sbuf = (float*)bufA;
    const float* xp = x + row * DIM;
    float* xo = g_xmid + row * DIM;
    float s = 0.f, ss = 0.f;
    #pragma unroll
    for (int j = 0; j < 4; j++) {
        int idx = tid + j * 256;
        float v = xp[idx] + mixed[j];
        xo[idx] = v;
        sbuf[idx] = v;
        s += v; ss += v * v;
    }
    float2 tot = block_reduce2(make_float2(s, ss), bufB);
    float mu = tot.x * (1.0f / DIM);
    float var = tot.y * (1.0f / DIM) - mu * mu;
    float rstd = rsqrtf(var + 1e-5f);
    float4 vv = ((const float4*)sbuf)[tid];
    float4 gg = ((const float4*)g)[tid];
    float4 bb = ((const float4*)b)[tid];
    float y0 = (vv.x - mu) * rstd * gg.x + bb.x;
    float y1 = (vv.y - mu) * rstd * gg.y + bb.y;
    float y2 = (vv.z - mu) * rstd * gg.z + bb.z;
    float y3 = (vv.w - mu) * rstd * gg.w + bb.w;
    uint32_t h0, l0, h1, l1;
    split2(y0, y1, h0, l0);
    split2(y2, y3, h1, l1);
    uint32_t* hw = (uint32_t*)ohi;
    uint32_t* lw = (uint32_t*)olo;
    size_t wb = row * 512 + tid * 2;
    hw[wb] = h0; hw[wb + 1] = h1;
    lw[wb] = l0; lw[wb + 1] = l1;
}

// ================== bf16x3 mma.sync GEMM, 256x128 CTA tile ==================
// 256 threads, 8 warps (4 m x 2 n), warp tile 64x64 (identical per-warp code
// to the proven R5 kernel), BK=32, 2-stage cp.async.
// SMEM per stage: Ahi(20K)|Alo(20K)|Bhi(10K)|Blo(10K) = 60KB; rows 80B stride.
// EPI: 0 = bias -> Cf ; 1 = bias + GELU -> Chi/Clo planes ; 2 = bias+res -> Cf
#define A_PL_B 20480u
#define B_PL_B 10240u
#define STAGE_B 61440u
#define STAGE_W 15360u
#define SMEM_GEMM (2 * STAGE_B)           // 122880

template<int EPI>
__global__ __launch_bounds__(256) void mma_gemm(
    const uint16_t* __restrict__ Ahi, const uint16_t* __restrict__ Alo,
    const uint16_t* __restrict__ Bhi, const uint16_t* __restrict__ Blo,
    const float* __restrict__ bias, const float* __restrict__ res,
    float* __restrict__ Cf, uint32_t* __restrict__ Chi, uint32_t* __restrict__ Clo,
    int N, int K)
{
    extern __shared__ uint32_t smu[];
    uint32_t su = smem_u32(smu);

    int tid = threadIdx.x;
    int wid = tid >> 5;
    int lane = tid & 31;
    int wm = wid & 3;        // 0..3 -> 64-row slice of 256
    int wn = wid >> 2;       // 0..1 -> 64-col slice of 128
    int bx = blockIdx.x, by = blockIdx.y;
    int gq = lane >> 2, tq = lane & 3;

    // loads: A row = tid (256 rows); B row = tid>>1, chunk pair = (tid&1)*2
    const uint16_t* aH = Ahi + (size_t)(by * 256 + tid) * K;
    const uint16_t* aL = Alo + (size_t)(by * 256 + tid) * K;
    int brow = tid >> 1;
    int bcp = (tid & 1) * 2;
    const uint16_t* bH = Bhi + (size_t)(bx * 128 + brow) * K;
    const uint16_t* bL = Blo + (size_t)(bx * 128 + brow) * K;

    #define LOAD_STAGE(s, k0) do { \
        uint32_t _sb = su + (uint32_t)(s) * STAGE_B; \
        uint32_t _da = _sb + (uint32_t)tid * 80u; \
        _Pragma("unroll") \
        for (int c = 0; c < 4; c++) { \
            cpa16(_da + c * 16,           aH + (k0) + c * 8); \
            cpa16(_da + A_PL_B + c * 16,  aL + (k0) + c * 8); \
        } \
        uint32_t _db = _sb + 2 * A_PL_B + (uint32_t)brow * 80u + (uint32_t)bcp * 16u; \
        _Pragma("unroll") \
        for (int c = 0; c < 2; c++) { \
            cpa16(_db + c * 16,           bH + (k0) + (bcp + c) * 8); \
            cpa16(_db + B_PL_B + c * 16,  bL + (k0) + (bcp + c) * 8); \
        } \
        asm volatile("cp.async.commit_group;" ::: "memory"); \
    } while (0)

    float acc[4][8][4];
    #pragma unroll
    for (int mt = 0; mt < 4; mt++)
        #pragma unroll
        for (int nt = 0; nt < 8; nt++)
            #pragma unroll
            for (int i = 0; i < 4; i++) acc[mt][nt][i] = 0.f;

    int KT = K >> 5;
    LOAD_STAGE(0, 0);

    int aBase0 = (wm * 64 + gq) * 20 + tq;
    int bBase0 = (wn * 64 + gq) * 20 + tq;

    for (int it = 0; it < KT; it++) {
        asm volatile("cp.async.wait_group 0;" ::: "memory");
        __syncthreads();
        if (it + 1 < KT) LOAD_STAGE((it + 1) & 1, (it + 1) * 32);

        int s = it & 1;
        const uint32_t* ah_t = smu + s * STAGE_W;
        const uint32_t* al_t = ah_t + 5120;
        const uint32_t* bh_t = ah_t + 10240;
        const uint32_t* bl_t = ah_t + 12800;

        #pragma unroll
        for (int ks = 0; ks < 2; ks++) {
            int ko = ks * 8;
            uint32_t ah[4][4], al[4][4], bb[8][2];
            #pragma unroll
            for (int mt = 0; mt < 4; mt++) {
                int base = aBase0 + mt * 320 + ko;
                ah[mt][0] = ah_t[base];
                ah[mt][1] = ah_t[base + 160];
                ah[mt][2] = ah_t[base + 4];
                ah[mt][3] = ah_t[base + 164];
                al[mt][0] = al_t[base];
                al[mt][1] = al_t[base + 160];
                al[mt][2] = al_t[base + 4];
                al[mt][3] = al_t[base + 164];
            }
            #pragma unroll
            for (int nt = 0; nt < 8; nt++) {
                int base = bBase0 + nt * 160 + ko;
                bb[nt][0] = bh_t[base];
                bb[nt][1] = bh_t[base + 4];
            }
            #pragma unroll
            for (int mt = 0; mt < 4; mt++)
                #pragma unroll
                for (int nt = 0; nt < 8; nt++) {
                    mma_bf16(acc[mt][nt], ah[mt], bb[nt]);
                    mma_bf16(acc[mt][nt], al[mt], bb[nt]);
                }
            #pragma unroll
            for (int nt = 0; nt < 8; nt++) {
                int base = bBase0 + nt * 160 + ko;
                bb[nt][0] = bl_t[base];
                bb[nt][1] = bl_t[base + 4];
            }
            #pragma unroll
            for (int mt = 0; mt < 4; mt++)
                #pragma unroll
                for (int nt = 0; nt < 8; nt++)
                    mma_bf16(acc[mt][nt], ah[mt], bb[nt]);
        }
        __syncthreads();
    }

    // ---- epilogue ----
    #pragma unroll
    for (int mt = 0; mt < 4; mt++) {
        #pragma unroll
        for (int nt = 0; nt < 8; nt++) {
            int r0 = by * 256 + wm * 64 + mt * 16 + gq;
            int c0 = bx * 128 + wn * 64 + nt * 8 + tq * 2;
            float b0 = bias[c0], b1 = bias[c0 + 1];
            #pragma unroll
            for (int half = 0; half < 2; half++) {
                size_t r = r0 + half * 8;
                float v0 = acc[mt][nt][half * 2 + 0] + b0;
                float v1 = acc[mt][nt][half * 2 + 1] + b1;
                if (EPI == 1) {
                    v0 = 0.5f * v0 * (1.0f + erff(v0 * 0.70710678118654752f));
                    v1 = 0.5f * v1 * (1.0f + erff(v1 * 0.70710678118654752f));
                    uint32_t hw, lw;
                    split2(v0, v1, hw, lw);
                    size_t widx = (r * (size_t)N + c0) >> 1;
                    Chi[widx] = hw;
                    Clo[widx] = lw;
                } else {
                    if (EPI == 2) {
                        float2 rv = *(const float2*)(res + r * (size_t)N + c0);
                        v0 += rv.x; v1 += rv.y;
                    }
                    float2 o; o.x = v0; o.y = v1;
                    *(float2*)(Cf + r * (size_t)N + c0) = o;
                }
            }
        }
    }
}

// ---------------- launch ----------------
extern "C" void kernel_launch(void* const* d_in, const int* in_sizes, int n_in,
                              void* d_out, int out_size)
{
    const float* x     = (const float*)d_in[0];
    const float* Wq    = (const float*)d_in[1];
    const float* bq    = (const float*)d_in[2];
    const float* Wk    = (const float*)d_in[3];
    const float* bk    = (const float*)d_in[4];
    const float* Wv    = (const float*)d_in[5];
    const float* bv    = (const float*)d_in[6];
    const float* ln1_g = (const float*)d_in[7];
    const float* ln1_b = (const float*)d_in[8];
    const float* ln2_g = (const float*)d_in[9];
    const float* ln2_b = (const float*)d_in[10];
    const float* W1    = (const float*)d_in[11];
    const float* b1    = (const float*)d_in[12];
    const float* W2    = (const float*)d_in[13];
    const float* b2    = (const float*)d_in[14];
    float* out = (float*)d_out;

    uint16_t *hHi, *hLo, *h2Hi, *h2Lo, *m1Hi, *m1Lo;
    uint16_t *WqkvHi, *WqkvLo, *W1Hi, *W1Lo, *W2Hi, *W2Lo;
    float *qkv, *xmid, *bqkv;
    cudaGetSymbolAddress((void**)&hHi,   g_h_hi);
    cudaGetSymbolAddress((void**)&hLo,   g_h_lo);
    cudaGetSymbolAddress((void**)&h2Hi,  g_h2_hi);
    cudaGetSymbolAddress((void**)&h2Lo,  g_h2_lo);
    cudaGetSymbolAddress((void**)&m1Hi,  g_m1_hi);
    cudaGetSymbolAddress((void**)&m1Lo,  g_m1_lo);
    cudaGetSymbolAddress((void**)&WqkvHi, g_Wqkv_hi);
    cudaGetSymbolAddress((void**)&WqkvLo, g_Wqkv_lo);
    cudaGetSymbolAddress((void**)&W1Hi,  g_W1_hi);
    cudaGetSymbolAddress((void**)&W1Lo,  g_W1_lo);
    cudaGetSymbolAddress((void**)&W2Hi,  g_W2_hi);
    cudaGetSymbolAddress((void**)&W2Lo,  g_W2_lo);
    cudaGetSymbolAddress((void**)&qkv,   g_qkv);
    cudaGetSymbolAddress((void**)&xmid,  g_xmid);
    cudaGetSymbolAddress((void**)&bqkv,  g_bqkv);

    cudaFuncSetAttribute(mma_gemm<0>, cudaFuncAttributeMaxDynamicSharedMemorySize, SMEM_GEMM);
    cudaFuncSetAttribute(mma_gemm<1>, cudaFuncAttributeMaxDynamicSharedMemorySize, SMEM_GEMM);
    cudaFuncSetAttribute(mma_gemm<2>, cudaFuncAttributeMaxDynamicSharedMemorySize, SMEM_GEMM);

    init_tw_kernel<<<1, 512>>>();
    bias_concat_kernel<<<NQKV / 256, 256>>>(bq, bk, bv);

    // weights -> transposed bf16 hi/lo planes
    transpose_split_kernel<<<dim3(32, 32), dim3(32, 8)>>>(Wq, WqkvHi, WqkvLo, DIM, DIM);
    transpose_split_kernel<<<dim3(32, 32), dim3(32, 8)>>>(Wk, WqkvHi + (size_t)1024 * DIM, WqkvLo + (size_t)1024 * DIM, DIM, DIM);
    transpose_split_kernel<<<dim3(32, 32), dim3(32, 8)>>>(Wv, WqkvHi + (size_t)2048 * DIM, WqkvLo + (size_t)2048 * DIM, DIM, DIM);
    transpose_split_kernel<<<dim3(128, 32), dim3(32, 8)>>>(W1, W1Hi, W1Lo, DIM, HID);
    transpose_split_kernel<<<dim3(32, 128), dim3(32, 8)>>>(W2, W2Hi, W2Lo, HID, DIM);

    // LN1 -> h planes
    ln_split_kernel<<<NROW, 256>>>(x, ln1_g, ln1_b, hHi, hLo);

    // fused QKV projection (256x128 tiles)
    mma_gemm<0><<<dim3(NQKV / 128, NROW / 256), 256, SMEM_GEMM>>>(
        hHi, hLo, WqkvHi, WqkvLo, bqkv, nullptr, qkv, nullptr, nullptr, NQKV, DIM);

    // fused FFT + normalize for q,k,v
    fft_qkv_kernel<<<NROW, 256>>>();

    // causal cumsum in Fourier domain, fused * conj(Q̂)
    chain_partial_kernel<<<(NBATCH * CHUNKS * DIM) / 256, 256>>>();
    chain_apply_kernel<<<(NBATCH * CHUNKS * DIM) / 256, 256>>>();

    // inverse FFT + residual + LN2 (emits xmid fp32 + h2 planes)
    ifft_res_ln_split_kernel<<<NROW, 256>>>(x, ln2_g, ln2_b, h2Hi, h2Lo);

    // MLP
    mma_gemm<1><<<dim3(HID / 128, NROW / 256), 256, SMEM_GEMM>>>(
        h2Hi, h2Lo, W1Hi, W1Lo, b1, nullptr, nullptr,
        (uint32_t*)m1Hi, (uint32_t*)m1Lo, HID, DIM);
    mma_gemm<2><<<dim3(DIM / 128, NROW / 256), 256, SMEM_GEMM>>>(
        m1Hi, m1Lo, W2Hi, W2Lo, b2, xmid, out, nullptr, nullptr, DIM, HID);

    (void)in_sizes; (void)n_in; (void)out_size;
}

// round 8
// speedup vs baseline: 1.1656x; 1.0545x over previous
#include <cuda_runtime.h>
#include <math.h>
#include <math_constants.h>
#include <stdint.h>

#define NROW 8192   // B*S
#define DIM  1024
#define SEQ  2048
#define NBATCH 4
#define HID  4096
#define CHUNKS 16
#define TCHUNK (SEQ / CHUNKS)   // 128
#define NQKV 3072

// ---------------- scratch (static device globals; no runtime alloc) ----------
__device__ uint16_t g_h_hi[(size_t)NROW * DIM];
__device__ uint16_t g_h_lo[(size_t)NROW * DIM];
__device__ uint16_t g_h2_hi[(size_t)NROW * DIM];
__device__ uint16_t g_h2_lo[(size_t)NROW * DIM];
__device__ uint16_t g_m1_hi[(size_t)NROW * HID];
__device__ uint16_t g_m1_lo[(size_t)NROW * HID];
__device__ uint16_t g_Wqkv_hi[(size_t)NQKV * DIM];
__device__ uint16_t g_Wqkv_lo[(size_t)NQKV * DIM];
__device__ uint16_t g_W1_hi[(size_t)HID * DIM];
__device__ uint16_t g_W1_lo[(size_t)HID * DIM];
__device__ uint16_t g_W2_hi[(size_t)DIM * HID];
__device__ uint16_t g_W2_lo[(size_t)DIM * HID];
__device__ float  g_qkv[(size_t)NROW * NQKV];
__device__ float  g_bqkv[NQKV];
__device__ float2 g_Qhat[(size_t)NROW * DIM];
__device__ float2 g_Mhat[(size_t)NROW * DIM];
__device__ float  g_xmid[(size_t)NROW * DIM];
__device__ float2 g_tw[512];
__device__ float2 g_part[NBATCH * CHUNKS * DIM];

// ---------------- helpers ----------------
__device__ __forceinline__ uint32_t smem_u32(const void* p) {
    uint32_t a;
    asm("{ .reg .u64 t; cvta.to.shared.u64 t, %1; cvt.u32.u64 %0, t; }" : "=r"(a) : "l"(p));
    return a;
}
// split pair (x0,x1) -> packed bf16x2 hi (low half = x0) and lo
__device__ __forceinline__ void split2(float x0, float x1, uint32_t& hi, uint32_t& lo) {
    uint32_t h;
    asm("cvt.rn.bf16x2.f32 %0, %1, %2;" : "=r"(h) : "f"(x1), "f"(x0));
    float h0 = __uint_as_float(h << 16);
    float h1 = __uint_as_float(h & 0xFFFF0000u);
    float l0 = x0 - h0;
    float l1 = x1 - h1;
    asm("cvt.rn.bf16x2.f32 %0, %1, %2;" : "=r"(lo) : "f"(l1), "f"(l0));
    hi = h;
}
__device__ __forceinline__ void mma_bf16(float* d, const uint32_t* a, const uint32_t* b) {
    asm volatile("mma.sync.aligned.m16n8k16.row.col.f32.bf16.bf16.f32 "
        "{%0,%1,%2,%3}, {%4,%5,%6,%7}, {%8,%9}, {%0,%1,%2,%3};"
        : "+f"(d[0]), "+f"(d[1]), "+f"(d[2]), "+f"(d[3])
        : "r"(a[0]), "r"(a[1]), "r"(a[2]), "r"(a[3]), "r"(b[0]), "r"(b[1]));
}
__device__ __forceinline__ void cpa16(uint32_t dst, const void* src) {
    asm volatile("cp.async.cg.shared.global [%0], [%1], 16;" :: "r"(dst), "l"(src) : "memory");
}
__device__ __forceinline__ float2 c_add(float2 a, float2 b){return make_float2(a.x+b.x,a.y+b.y);}
__device__ __forceinline__ float2 c_sub(float2 a, float2 b){return make_float2(a.x-b.x,a.y-b.y);}
__device__ __forceinline__ float2 c_mul(float2 a, float2 b){return make_float2(a.x*b.x-a.y*b.y,a.x*b.y+a.y*b.x);}
__device__ __forceinline__ float2 c_negi(float2 a){return make_float2(a.y,-a.x);}  // -i*a

// ---------------- twiddle init ----------------
__global__ void init_tw_kernel() {
    int i = threadIdx.x;
    double th = -2.0 * CUDART_PI * (double)i / 1024.0;
    g_tw[i] = make_float2((float)cos(th), (float)sin(th));
}

// ---------------- bias concat ----------------
__global__ void bias_concat_kernel(const float* bq, const float* bk, const float* bv) {
    int i = blockIdx.x * 256 + threadIdx.x;
    float v = (i < 1024) ? bq[i] : (i < 2048) ? bk[i - 1024] : bv[i - 2048];
    g_bqkv[i] = v;
}

// ---------------- weight transpose + bf16 split ----------------
__global__ __launch_bounds__(256) void transpose_split_kernel(
    const float* __restrict__ in, uint16_t* __restrict__ ohi,
    uint16_t* __restrict__ olo, int R, int C)
{
    __shared__ float t[32][33];
    int bx = blockIdx.x, by = blockIdx.y;
    int x = bx * 32 + threadIdx.x;
    int y0 = by * 32 + threadIdx.y;
    #pragma unroll
    for (int j = 0; j < 32; j += 8)
        t[threadIdx.y + j][threadIdx.x] = in[(size_t)(y0 + j) * C + x];
    __syncthreads();
    int tl = threadIdx.y * 32 + threadIdx.x;
    int kp = tl & 15;
    int nr0 = tl >> 4;
    uint32_t* hw32 = (uint32_t*)ohi;
    uint32_t* lw32 = (uint32_t*)olo;
    #pragma unroll
    for (int rep = 0; rep < 2; rep++) {
        int nrel = nr0 + rep * 16;
        size_t n = (size_t)bx * 32 + nrel;
        int kg = by * 32 + kp * 2;
        uint32_t hw, lw;
        split2(t[kp * 2][nrel], t[kp * 2 + 1][nrel], hw, lw);
        size_t widx = (n * (size_t)R + kg) >> 1;
        hw32[widx] = hw;
        lw32[widx] = lw;
    }
}

// ---------------- block reduction ----------------
__device__ __forceinline__ float2 block_reduce2(float2 v, float2* sh) {
    int tid = threadIdx.x;
    sh[tid] = v;
    __syncthreads();
    #pragma unroll
    for (int s = 128; s > 0; s >>= 1) {
        if (tid < s) {
            sh[tid].x += sh[tid + s].x;
            sh[tid].y += sh[tid + s].y;
        }
        __syncthreads();
    }
    float2 r = sh[0];
    __syncthreads();
    return r;
}

// ---------------- LayerNorm 1 -> bf16 hi/lo planes ----------------
__global__ __launch_bounds__(256) void ln_split_kernel(
    const float* __restrict__ x, const float* __restrict__ g,
    const float* __restrict__ b, uint16_t* __restrict__ ohi,
    uint16_t* __restrict__ olo)
{
    __shared__ float2 red[256];
    size_t row = blockIdx.x;
    int tid = threadIdx.x;
    float4 v = ((const float4*)(x + row * DIM))[tid];
    float s = v.x + v.y + v.z + v.w;
    float ss = v.x * v.x + v.y * v.y + v.z * v.z + v.w * v.w;
    float2 tot = block_reduce2(make_float2(s, ss), red);
    float mu = tot.x * (1.0f / DIM);
    float var = tot.y * (1.0f / DIM) - mu * mu;
    float rstd = rsqrtf(var + 1e-5f);
    float4 gg = ((const float4*)g)[tid];
    float4 bb = ((const float4*)b)[tid];
    float y0 = (v.x - mu) * rstd * gg.x + bb.x;
    float y1 = (v.y - mu) * rstd * gg.y + bb.y;
    float y2 = (v.z - mu) * rstd * gg.z + bb.z;
    float y3 = (v.w - mu) * rstd * gg.w + bb.w;
    uint32_t h0, l0, h1, l1;
    split2(y0, y1, h0, l0);
    split2(y2, y3, h1, l1);
    uint32_t* hw = (uint32_t*)ohi;
    uint32_t* lw = (uint32_t*)olo;
    size_t wb = row * 512 + tid * 2;
    hw[wb] = h0; hw[wb + 1] = h1;
    lw[wb] = l0; lw[wb + 1] = l1;
}

// -------- 1024-pt radix-4 Stockham FFT, bank-conflict-free swizzles --------
// 5 stages, 256 threads, math identical to the R6 (correctness-proven) radix-4.
// Only generations 1 and 2 of the ping-pong buffers need swizzling: stage-0
// stores (stride 4) and stage-1 stores (stride 16) are the only conflicted
// patterns; XOR swizzles inject the lane-varying high bits into bank bits.
__device__ __forceinline__ int swz(int g, int a) {
    if (g == 1) return a ^ ((a >> 4) & 3);
    if (g == 2) return a ^ ((a >> 2) & 0xC);
    return a;
}

__device__ __forceinline__ float2* fft1024(float2* bufA, float2* bufB) {
    float2* x = bufA;
    float2* y = bufB;
    int n4 = 256, s = 1;
    #pragma unroll
    for (int st = 0; st < 5; st++) {
        __syncthreads();
        int i = threadIdx.x;
        int p = i / s;
        int q = i - p * s;
        float2 w1 = g_tw[p * s];
        float2 w2 = g_tw[2 * p * s];
        float2 x0 = x[swz(st, q + s * p)];
        float2 x1 = x[swz(st, q + s * (p + n4))];
        float2 x2 = x[swz(st, q + s * (p + 2 * n4))];
        float2 x3 = x[swz(st, q + s * (p + 3 * n4))];
        float2 za0 = c_add(x0, x2);
        float2 za1 = c_mul(c_sub(x0, x2), w1);
        float2 zb0 = c_add(x1, x3);
        float2 zb1 = c_mul(c_negi(c_sub(x1, x3)), w1);
        int ob = q + s * 4 * p;
        y[swz(st + 1, ob)]         = c_add(za0, zb0);
        y[swz(st + 1, ob + s)]     = c_add(za1, zb1);
        y[swz(st + 1, ob + 2 * s)] = c_mul(c_sub(za0, zb0), w2);
        y[swz(st + 1, ob + 3 * s)] = c_mul(c_sub(za1, zb1), w2);
        float2* t = x; x = y; y = t;
        n4 >>= 2; s <<= 2;
    }
    __syncthreads();
    return x;   // bufB after 5 swaps; gen-5 layout = identity
}

// -------- fused QKV FFT: Q̂ -> g_Qhat ; K̂·V̂ -> g_Mhat (one block per row) ----
__global__ __launch_bounds__(256) void fft_qkv_kernel() {
    __shared__ __align__(16) float2 bufA[1024];
    __shared__ __align__(16) float2 bufB[1024];
    __shared__ __align__(16) float2 kbuf[1024];
    size_t row = blockIdx.x;
    int tid = threadIdx.x;
    const float* base = g_qkv + row * NQKV;

    // --- Q ---
    #pragma unroll
    for (int j = 0; j < 4; j++) {
        int idx = tid + j * 256;
        bufA[idx] = make_float2(base[idx], 0.f);
    }
    float2* res = fft1024(bufA, bufB);
    float2* qp = g_Qhat + row * DIM;
    #pragma unroll
    for (int j = 0; j < 4; j++) {
        int idx = tid + j * 256;
        float2 f = res[idx];
        float inv = 1.0f / fmaxf(sqrtf(f.x * f.x + f.y * f.y), 1e-8f);
        qp[idx] = make_float2(f.x * inv, f.y * inv);
    }
    __syncthreads();

    // --- K ---
    #pragma unroll
    for (int j = 0; j < 4; j++) {
        int idx = tid + j * 256;
        bufA[idx] = make_float2(base[1024 + idx], 0.f);
    }
    res = fft1024(bufA, bufB);
    #pragma unroll
    for (int j = 0; j < 4; j++) {
        int idx = tid + j * 256;
        float2 f = res[idx];
        float inv = 1.0f / fmaxf(sqrtf(f.x * f.x + f.y * f.y), 1e-8f);
        kbuf[idx] = make_float2(f.x * inv, f.y * inv);
    }
    __syncthreads();

    // --- V, multiply by K̂ ---
    #pragma unroll
    for (int j = 0; j < 4; j++) {
        int idx = tid + j * 256;
        bufA[idx] = make_float2(base[2048 + idx], 0.f);
    }
    res = fft1024(bufA, bufB);
    float2* mp = g_Mhat + row * DIM;
    #pragma unroll
    for (int j = 0; j < 4; j++) {
        int idx = tid + j * 256;
        float2 f = res[idx];
        float inv = 1.0f / fmaxf(sqrtf(f.x * f.x + f.y * f.y), 1e-8f);
        f.x *= inv; f.y *= inv;
        float2 k = kbuf[idx];
        mp[idx] = make_float2(k.x * f.x - k.y * f.y,
                              k.x * f.y + k.y * f.x);
    }
}

// ---------------- chain pass A: per-chunk partial sums ----------------
__global__ __launch_bounds__(256) void chain_partial_kernel() {
    int gid = blockIdx.x * 256 + threadIdx.x;
    int bin = gid & 1023;
    int chunk = (gid >> 10) & (CHUNKS - 1);
    int b = gid >> 14;
    size_t base = ((size_t)b * SEQ + (size_t)chunk * TCHUNK) * DIM + bin;
    float2 s = make_float2(0.f, 0.f);
    #pragma unroll 4
    for (int i = 0; i < TCHUNK; i++) {
        float2 p = g_Mhat[base + (size_t)i * DIM];
        s.x += p.x; s.y += p.y;
    }
    g_part[gid] = s;
}

// ---------------- chain pass B: scan within chunk + apply conj(Q̂) --------
__global__ __launch_bounds__(256) void chain_apply_kernel() {
    int gid = blockIdx.x * 256 + threadIdx.x;
    int bin = gid & 1023;
    int chunk = (gid >> 10) & (CHUNKS - 1);
    int b = gid >> 14;
    float2 acc = make_float2(0.f, 0.f);
    for (int c = 0; c < chunk; c++) {
        float2 p = g_part[((b * CHUNKS) + c) * 1024 + bin];
        acc.x += p.x; acc.y += p.y;
    }
    size_t base = ((size_t)b * SEQ + (size_t)chunk * TCHUNK) * DIM + bin;
    #pragma unroll 4
    for (int i = 0; i < TCHUNK; i++) {
        size_t off = base + (size_t)i * DIM;
        float2 p = g_Mhat[off];
        acc.x += p.x; acc.y += p.y;
        float2 q = g_Qhat[off];
        g_Mhat[off] = make_float2(acc.x * q.x + acc.y * q.y,
                                  acc.y * q.x - acc.x * q.y);
    }
}

// ------- inverse FFT + residual + LN2, emits xmid fp32 and h2 bf16 planes ----
__global__ __launch_bounds__(256) void ifft_res_ln_split_kernel(
    const float* __restrict__ x, const float* __restrict__ g,
    const float* __restrict__ b, uint16_t* __restrict__ ohi,
    uint16_t* __restrict__ olo)
{
    __shared__ __align__(16) float2 bufA[1024];
    __shared__ __align__(16) float2 bufB[1024];
    size_t row = blockIdx.x;
    int tid = threadIdx.x;
    const float2* mp = g_Mhat + row * DIM;
    #pragma unroll
    for (int j = 0; j < 4; j++) {
        int idx = tid + j * 256;
        float2 m = mp[idx];
        bufA[idx] = make_float2(m.x, -m.y);
    }
    float2* res = fft1024(bufA, bufB);   // = bufB
    float mixed[4];
    #pragma unroll
    for (int j = 0; j < 4; j++) mixed[j] = res[tid + j * 256].x * (1.0f / 1024.0f);
    __syncthreads();
    float* sbuf = (float*)bufA;          // bufA dead now
    const float* xp = x + row * DIM;
    float* xo = g_xmid + row * DIM;
    float s = 0.f, ss = 0.f;
    #pragma unroll
    for (int j = 0; j < 4; j++) {
        int idx = tid + j * 256;
        float v = xp[idx] + mixed[j];
        xo[idx] = v;
        sbuf[idx] = v;
        s += v; ss += v * v;
    }
    __syncthreads();                      // mixed reads of bufB done before reuse
    float2 tot = block_reduce2(make_float2(s, ss), bufB);
    float mu = tot.x * (1.0f / DIM);
    float var = tot.y * (1.0f / DIM) - mu * mu;
    float rstd = rsqrtf(var + 1e-5f);
    float4 vv = ((const float4*)sbuf)[tid];
    float4 gg = ((const float4*)g)[tid];
    float4 bb = ((const float4*)b)[tid];
    float y0 = (vv.x - mu) * rstd * gg.x + bb.x;
    float y1 = (vv.y - mu) * rstd * gg.y + bb.y;
    float y2 = (vv.z - mu) * rstd * gg.z + bb.z;
    float y3 = (vv.w - mu) * rstd * gg.w + bb.w;
    uint32_t h0, l0, h1, l1;
    split2(y0, y1, h0, l0);
    split2(y2, y3, h1, l1);
    uint32_t* hw = (uint32_t*)ohi;
    uint32_t* lw = (uint32_t*)olo;
    size_t wb = row * 512 + tid * 2;
    hw[wb] = h0; hw[wb + 1] = h1;
    lw[wb] = l0; lw[wb + 1] = l1;
}

// ================== bf16x3 mma.sync GEMM, 256x128 CTA tile ==================
// (unchanged from R7 — measured at ~HMMA instruction-rate peak)
#define A_PL_B 20480u
#define B_PL_B 10240u
#define STAGE_B 61440u
#define STAGE_W 15360u
#define SMEM_GEMM (2 * STAGE_B)           // 122880

template<int EPI>
__global__ __launch_bounds__(256) void mma_gemm(
    const uint16_t* __restrict__ Ahi, const uint16_t* __restrict__ Alo,
    const uint16_t* __restrict__ Bhi, const uint16_t* __restrict__ Blo,
    const float* __restrict__ bias, const float* __restrict__ res,
    float* __restrict__ Cf, uint32_t* __restrict__ Chi, uint32_t* __restrict__ Clo,
    int N, int K)
{
    extern __shared__ uint32_t smu[];
    uint32_t su = smem_u32(smu);

    int tid = threadIdx.x;
    int wid = tid >> 5;
    int lane = tid & 31;
    int wm = wid & 3;
    int wn = wid >> 2;
    int bx = blockIdx.x, by = blockIdx.y;
    int gq = lane >> 2, tq = lane & 3;

    const uint16_t* aH = Ahi + (size_t)(by * 256 + tid) * K;
    const uint16_t* aL = Alo + (size_t)(by * 256 + tid) * K;
    int brow = tid >> 1;
    int bcp = (tid & 1) * 2;
    const uint16_t* bH = Bhi + (size_t)(bx * 128 + brow) * K;
    const uint16_t* bL = Blo + (size_t)(bx * 128 + brow) * K;

    #define LOAD_STAGE(s, k0) do { \
        uint32_t _sb = su + (uint32_t)(s) * STAGE_B; \
        uint32_t _da = _sb + (uint32_t)tid * 80u; \
        _Pragma("unroll") \
        for (int c = 0; c < 4; c++) { \
            cpa16(_da + c * 16,           aH + (k0) + c * 8); \
            cpa16(_da + A_PL_B + c * 16,  aL + (k0) + c * 8); \
        } \
        uint32_t _db = _sb + 2 * A_PL_B + (uint32_t)brow * 80u + (uint32_t)bcp * 16u; \
        _Pragma("unroll") \
        for (int c = 0; c < 2; c++) { \
            cpa16(_db + c * 16,           bH + (k0) + (bcp + c) * 8); \
            cpa16(_db + B_PL_B + c * 16,  bL + (k0) + (bcp + c) * 8); \
        } \
        asm volatile("cp.async.commit_group;" ::: "memory"); \
    } while (0)

    float acc[4][8][4];
    #pragma unroll
    for (int mt = 0; mt < 4; mt++)
        #pragma unroll
        for (int nt = 0; nt < 8; nt++)
            #pragma unroll
            for (int i = 0; i < 4; i++) acc[mt][nt][i] = 0.f;

    int KT = K >> 5;
    LOAD_STAGE(0, 0);

    int aBase0 = (wm * 64 + gq) * 20 + tq;
    int bBase0 = (wn * 64 + gq) * 20 + tq;

    for (int it = 0; it < KT; it++) {
        asm volatile("cp.async.wait_group 0;" ::: "memory");
        __syncthreads();
        if (it + 1 < KT) LOAD_STAGE((it + 1) & 1, (it + 1) * 32);

        int s = it & 1;
        const uint32_t* ah_t = smu + s * STAGE_W;
        const uint32_t* al_t = ah_t + 5120;
        const uint32_t* bh_t = ah_t + 10240;
        const uint32_t* bl_t = ah_t + 12800;

        #pragma unroll
        for (int ks = 0; ks < 2; ks++) {
            int ko = ks * 8;
            uint32_t ah[4][4], al[4][4], bb[8][2];
            #pragma unroll
            for (int mt = 0; mt < 4; mt++) {
                int base = aBase0 + mt * 320 + ko;
                ah[mt][0] = ah_t[base];
                ah[mt][1] = ah_t[base + 160];
                ah[mt][2] = ah_t[base + 4];
                ah[mt][3] = ah_t[base + 164];
                al[mt][0] = al_t[base];
                al[mt][1] = al_t[base + 160];
                al[mt][2] = al_t[base + 4];
                al[mt][3] = al_t[base + 164];
            }
            #pragma unroll
            for (int nt = 0; nt < 8; nt++) {
                int base = bBase0 + nt * 160 + ko;
                bb[nt][0] = bh_t[base];
                bb[nt][1] = bh_t[base + 4];
            }
            #pragma unroll
            for (int mt = 0; mt < 4; mt++)
                #pragma unroll
                for (int nt = 0; nt < 8; nt++) {
                    mma_bf16(acc[mt][nt], ah[mt], bb[nt]);
                    mma_bf16(acc[mt][nt], al[mt], bb[nt]);
                }
            #pragma unroll
            for (int nt = 0; nt < 8; nt++) {
                int base = bBase0 + nt * 160 + ko;
                bb[nt][0] = bl_t[base];
                bb[nt][1] = bl_t[base + 4];
            }
            #pragma unroll
            for (int mt = 0; mt < 4; mt++)
                #pragma unroll
                for (int nt = 0; nt < 8; nt++)
                    mma_bf16(acc[mt][nt], ah[mt], bb[nt]);
        }
        __syncthreads();
    }

    // ---- epilogue ----
    #pragma unroll
    for (int mt = 0; mt < 4; mt++) {
        #pragma unroll
        for (int nt = 0; nt < 8; nt++) {
            int r0 = by * 256 + wm * 64 + mt * 16 + gq;
            int c0 = bx * 128 + wn * 64 + nt * 8 + tq * 2;
            float b0 = bias[c0], b1 = bias[c0 + 1];
            #pragma unroll
            for (int half = 0; half < 2; half++) {
                size_t r = r0 + half * 8;
                float v0 = acc[mt][nt][half * 2 + 0] + b0;
                float v1 = acc[mt][nt][half * 2 + 1] + b1;
                if (EPI == 1) {
                    v0 = 0.5f * v0 * (1.0f + erff(v0 * 0.70710678118654752f));
                    v1 = 0.5f * v1 * (1.0f + erff(v1 * 0.70710678118654752f));
                    uint32_t hw, lw;
                    split2(v0, v1, hw, lw);
                    size_t widx = (r * (size_t)N + c0) >> 1;
                    Chi[widx] = hw;
                    Clo[widx] = lw;
                } else {
                    if (EPI == 2) {
                        float2 rv = *(const float2*)(res + r * (size_t)N + c0);
                        v0 += rv.x; v1 += rv.y;
                    }
                    float2 o; o.x = v0; o.y = v1;
                    *(float2*)(Cf + r * (size_t)N + c0) = o;
                }
            }
        }
    }
}

// ---------------- launch ----------------
extern "C" void kernel_launch(void* const* d_in, const int* in_sizes, int n_in,
                              void* d_out, int out_size)
{
    const float* x     = (const float*)d_in[0];
    const float* Wq    = (const float*)d_in[1];
    const float* bq    = (const float*)d_in[2];
    const float* Wk    = (const float*)d_in[3];
    const float* bk    = (const float*)d_in[4];
    const float* Wv    = (const float*)d_in[5];
    const float* bv    = (const float*)d_in[6];
    const float* ln1_g = (const float*)d_in[7];
    const float* ln1_b = (const float*)d_in[8];
    const float* ln2_g = (const float*)d_in[9];
    const float* ln2_b = (const float*)d_in[10];
    const float* W1    = (const float*)d_in[11];
    const float* b1    = (const float*)d_in[12];
    const float* W2    = (const float*)d_in[13];
    const float* b2    = (const float*)d_in[14];
    float* out = (float*)d_out;

    uint16_t *hHi, *hLo, *h2Hi, *h2Lo, *m1Hi, *m1Lo;
    uint16_t *WqkvHi, *WqkvLo, *W1Hi, *W1Lo, *W2Hi, *W2Lo;
    float *qkv, *xmid, *bqkv;
    cudaGetSymbolAddress((void**)&hHi,   g_h_hi);
    cudaGetSymbolAddress((void**)&hLo,   g_h_lo);
    cudaGetSymbolAddress((void**)&h2Hi,  g_h2_hi);
    cudaGetSymbolAddress((void**)&h2Lo,  g_h2_lo);
    cudaGetSymbolAddress((void**)&m1Hi,  g_m1_hi);
    cudaGetSymbolAddress((void**)&m1Lo,  g_m1_lo);
    cudaGetSymbolAddress((void**)&WqkvHi, g_Wqkv_hi);
    cudaGetSymbolAddress((void**)&WqkvLo, g_Wqkv_lo);
    cudaGetSymbolAddress((void**)&W1Hi,  g_W1_hi);
    cudaGetSymbolAddress((void**)&W1Lo,  g_W1_lo);
    cudaGetSymbolAddress((void**)&W2Hi,  g_W2_hi);
    cudaGetSymbolAddress((void**)&W2Lo,  g_W2_lo);
    cudaGetSymbolAddress((void**)&qkv,   g_qkv);
    cudaGetSymbolAddress((void**)&xmid,  g_xmid);
    cudaGetSymbolAddress((void**)&bqkv,  g_bqkv);

    cudaFuncSetAttribute(mma_gemm<0>, cudaFuncAttributeMaxDynamicSharedMemorySize, SMEM_GEMM);
    cudaFuncSetAttribute(mma_gemm<1>, cudaFuncAttributeMaxDynamicSharedMemorySize, SMEM_GEMM);
    cudaFuncSetAttribute(mma_gemm<2>, cudaFuncAttributeMaxDynamicSharedMemorySize, SMEM_GEMM);

    init_tw_kernel<<<1, 512>>>();
    bias_concat_kernel<<<NQKV / 256, 256>>>(bq, bk, bv);

    // weights -> transposed bf16 hi/lo planes
    transpose_split_kernel<<<dim3(32, 32), dim3(32, 8)>>>(Wq, WqkvHi, WqkvLo, DIM, DIM);
    transpose_split_kernel<<<dim3(32, 32), dim3(32, 8)>>>(Wk, WqkvHi + (size_t)1024 * DIM, WqkvLo + (size_t)1024 * DIM, DIM, DIM);
    transpose_split_kernel<<<dim3(32, 32), dim3(32, 8)>>>(Wv, WqkvHi + (size_t)2048 * DIM, WqkvLo + (size_t)2048 * DIM, DIM, DIM);
    transpose_split_kernel<<<dim3(128, 32), dim3(32, 8)>>>(W1, W1Hi, W1Lo, DIM, HID);
    transpose_split_kernel<<<dim3(32, 128), dim3(32, 8)>>>(W2, W2Hi, W2Lo, HID, DIM);

    // LN1 -> h planes
    ln_split_kernel<<<NROW, 256>>>(x, ln1_g, ln1_b, hHi, hLo);

    // fused QKV projection (256x128 tiles)
    mma_gemm<0><<<dim3(NQKV / 128, NROW / 256), 256, SMEM_GEMM>>>(
        hHi, hLo, WqkvHi, WqkvLo, bqkv, nullptr, qkv, nullptr, nullptr, NQKV, DIM);

    // fused FFT + normalize for q,k,v
    fft_qkv_kernel<<<NROW, 256>>>();

    // causal cumsum in Fourier domain, fused * conj(Q̂)
    chain_partial_kernel<<<(NBATCH * CHUNKS * DIM) / 256, 256>>>();
    chain_apply_kernel<<<(NBATCH * CHUNKS * DIM) / 256, 256>>>();

    // inverse FFT + residual + LN2 (emits xmid fp32 + h2 planes)
    ifft_res_ln_split_kernel<<<NROW, 256>>>(x, ln2_g, ln2_b, h2Hi, h2Lo);

    // MLP
    mma_gemm<1><<<dim3(HID / 128, NROW / 256), 256, SMEM_GEMM>>>(
        h2Hi, h2Lo, W1Hi, W1Lo, b1, nullptr, nullptr,
        (uint32_t*)m1Hi, (uint32_t*)m1Lo, HID, DIM);
    mma_gemm<2><<<dim3(DIM / 128, NROW / 256), 256, SMEM_GEMM>>>(
        m1Hi, m1Lo, W2Hi, W2Lo, b2, xmid, out, nullptr, nullptr, DIM, HID);

    (void)in_sizes; (void)n_in; (void)out_size;
}